// round 16
// baseline (speedup 1.0000x reference)
#include <cuda_runtime.h>
#include <cuda_fp16.h>
#include <math.h>
#include <stdint.h>

#define BB 128
#define LL 31
#define TT 32
#define EE 512
#define TAGN 512
#define HH 1024
#define G4 4096
#define VV 30000

typedef __half h16;

// ---------------- device scratch ----------------
__device__ __align__(256) float d_gates[(size_t)4096 * 4096];   // gx (stores) + rec (atomics), rows t*128+b
__device__ __align__(256) float d_gt[(size_t)BB * G4];          // tag-gx + bias, rows b
__device__ __align__(256) float d_c[BB * HH];
__device__ __align__(256) h16 d_hfh[(size_t)4096 * 1024];       // h hi, rows t*128+b
__device__ __align__(256) h16 d_hfl[(size_t)4096 * 1024];       // h lo
__device__ __align__(256) h16 d_xeh[(size_t)4096 * 512];        // x embed-part hi, rows t*128+b
__device__ __align__(256) h16 d_xel[(size_t)4096 * 512];
__device__ __align__(256) h16 d_tgh[(size_t)BB * 512];          // tags hi/lo
__device__ __align__(256) h16 d_tgl[(size_t)BB * 512];
__device__ __align__(256) h16 d_Wlf[(size_t)VV * 1024];         // W_lin fp16
__device__ __align__(256) h16 d_Wieh[(size_t)4096 * 512];       // W_ih embed cols hi/lo
__device__ __align__(256) h16 d_Wiel[(size_t)4096 * 512];
__device__ __align__(256) h16 d_With[(size_t)4096 * 512];       // W_ih tag cols hi/lo
__device__ __align__(256) h16 d_Witl[(size_t)4096 * 512];
__device__ __align__(256) h16 d_Whhh[(size_t)4096 * 1024];      // W_hh hi/lo
__device__ __align__(256) h16 d_Whhl[(size_t)4096 * 1024];
__device__ __align__(256) float d_bias2[G4];
__device__ int d_rowmap[4096];

// ---------------- asm helpers (portable to plain sm_103) ----------------
__device__ __forceinline__ uint32_t smem_u32(const void* p) {
    uint32_t a;
    asm("{ .reg .u64 t; cvta.to.shared.u64 t, %1; cvt.u32.u64 %0, t; }" : "=r"(a) : "l"(p));
    return a;
}
#define CP16(dst, src) asm volatile("cp.async.cg.shared.global [%0], [%1], 16;" :: "r"(dst), "l"(src))
#define CP_COMMIT()    asm volatile("cp.async.commit_group;")
#define CP_WAIT1()     asm volatile("cp.async.wait_group 1;")
#define CP_WAIT0()     asm volatile("cp.async.wait_group 0;")

__device__ __forceinline__ void ldsm4(uint32_t addr, uint32_t* r) {
    asm volatile("ldmatrix.sync.aligned.m8n8.x4.shared.b16 {%0,%1,%2,%3}, [%4];"
                 : "=r"(r[0]), "=r"(r[1]), "=r"(r[2]), "=r"(r[3]) : "r"(addr));
}
__device__ __forceinline__ void mma16816(float* d, const uint32_t* a, uint32_t b0, uint32_t b1) {
    asm volatile(
        "mma.sync.aligned.m16n8k16.row.col.f32.f16.f16.f32 "
        "{%0,%1,%2,%3}, {%4,%5,%6,%7}, {%8,%9}, {%0,%1,%2,%3};"
        : "+f"(d[0]), "+f"(d[1]), "+f"(d[2]), "+f"(d[3])
        : "r"(a[0]), "r"(a[1]), "r"(a[2]), "r"(a[3]), "r"(b0), "r"(b1));
}

// ---------------- small kernels ----------------
__global__ void meta_kernel(const int* __restrict__ lengths) {
    __shared__ int len[BB];
    __shared__ int nt[TT];
    __shared__ int off[TT];
    int tid = threadIdx.x;
    len[tid] = lengths[tid];
    __syncthreads();
    if (tid < TT) {
        int c = 0;
        for (int b = 0; b < BB; b++) c += (len[b] > tid) ? 1 : 0;
        nt[tid] = c;
    }
    __syncthreads();
    if (tid == 0) {
        int s = 0;
        for (int t = 0; t < TT; t++) { off[t] = s; s += nt[t]; }
    }
    __syncthreads();
    for (int t = 0; t < TT; t++) {
        int n = nt[t], o = off[t];
        for (int b = tid; b < n; b += blockDim.x)
            d_rowmap[o + b] = t * BB + b;
    }
}

// generic fp32 -> fp16 hi/lo split
__global__ void conv_split(const float* __restrict__ s, h16* __restrict__ hi,
                           h16* __restrict__ lo, int n4) {
    int i = blockIdx.x * blockDim.x + threadIdx.x;
    if (i >= n4) return;
    float4 v = reinterpret_cast<const float4*>(s)[i];
    float vv[4] = {v.x, v.y, v.z, v.w};
    h16 hh[4], ll[4];
#pragma unroll
    for (int j = 0; j < 4; j++) {
        hh[j] = __float2half(vv[j]);
        ll[j] = __float2half(vv[j] - __half2float(hh[j]));
    }
    reinterpret_cast<uint2*>(hi)[i] = *reinterpret_cast<uint2*>(hh);
    reinterpret_cast<uint2*>(lo)[i] = *reinterpret_cast<uint2*>(ll);
}

// fp32 -> fp16 round (single)
__global__ void conv_round(const float* __restrict__ s, h16* __restrict__ o, int n4) {
    int i = blockIdx.x * blockDim.x + threadIdx.x;
    if (i >= n4) return;
    float4 v = reinterpret_cast<const float4*>(s)[i];
    h16 hh[4] = {__float2half(v.x), __float2half(v.y), __float2half(v.z), __float2half(v.w)};
    reinterpret_cast<uint2*>(o)[i] = *reinterpret_cast<uint2*>(hh);
}

// split W_ih [4096][1024] column-wise into embed (k<512) and tag (k>=512) hi/lo
__global__ void conv_wih(const float* __restrict__ W_ih) {
    int row = blockIdx.x;
    int k = threadIdx.x * 4;
    float4 v = *reinterpret_cast<const float4*>(W_ih + (size_t)row * 1024 + k);
    float vv[4] = {v.x, v.y, v.z, v.w};
    h16 hh[4], ll[4];
#pragma unroll
    for (int j = 0; j < 4; j++) {
        hh[j] = __float2half(vv[j]);
        ll[j] = __float2half(vv[j] - __half2float(hh[j]));
    }
    if (k < EE) {
        size_t o = ((size_t)row * 512 + k) >> 2;
        reinterpret_cast<uint2*>(d_Wieh)[o] = *reinterpret_cast<uint2*>(hh);
        reinterpret_cast<uint2*>(d_Wiel)[o] = *reinterpret_cast<uint2*>(ll);
    } else {
        size_t o = ((size_t)row * 512 + (k - EE)) >> 2;
        reinterpret_cast<uint2*>(d_With)[o] = *reinterpret_cast<uint2*>(hh);
        reinterpret_cast<uint2*>(d_Witl)[o] = *reinterpret_cast<uint2*>(ll);
    }
}

__global__ void bias2_k(const float* __restrict__ b_ih, const float* __restrict__ b_hh) {
    int i = blockIdx.x * blockDim.x + threadIdx.x;
    if (i < G4) d_bias2[i] = b_ih[i] + b_hh[i];
}

// gather embed-part x rows (features for t=0, embeddings else), rows t*128+b
__global__ void conv_xt(const float* __restrict__ features,
                        const int* __restrict__ captions, const float* __restrict__ W_embed) {
    int r = blockIdx.x;
    int t = r >> 7, b = r & 127;
    int k = threadIdx.x * 4;
    const float* src = (t == 0) ? (features + (size_t)b * EE)
                                : (W_embed + (size_t)captions[b * LL + (t - 1)] * EE);
    float4 v = *reinterpret_cast<const float4*>(src + k);
    float vv[4] = {v.x, v.y, v.z, v.w};
    h16 hh[4], ll[4];
#pragma unroll
    for (int j = 0; j < 4; j++) {
        hh[j] = __float2half(vv[j]);
        ll[j] = __float2half(vv[j] - __half2float(hh[j]));
    }
    size_t o = ((size_t)r * 512 + k) >> 2;
    reinterpret_cast<uint2*>(d_xeh)[o] = *reinterpret_cast<uint2*>(hh);
    reinterpret_cast<uint2*>(d_xel)[o] = *reinterpret_cast<uint2*>(ll);
}

// split tags [128][512] hi/lo
__global__ void conv_tags(const float* __restrict__ tags) {
    int b = blockIdx.x;
    int k = threadIdx.x * 4;
    float4 v = *reinterpret_cast<const float4*>(tags + (size_t)b * TAGN + k);
    float vv[4] = {v.x, v.y, v.z, v.w};
    h16 hh[4], ll[4];
#pragma unroll
    for (int j = 0; j < 4; j++) {
        hh[j] = __float2half(vv[j]);
        ll[j] = __float2half(vv[j] - __half2float(hh[j]));
    }
    size_t o = ((size_t)b * 512 + k) >> 2;
    reinterpret_cast<uint2*>(d_tgh)[o] = *reinterpret_cast<uint2*>(hh);
    reinterpret_cast<uint2*>(d_tgl)[o] = *reinterpret_cast<uint2*>(ll);
}

// LSTM elementwise: gates = d_gates(row t*128+b; gx stores + rec atomics) + d_gt(row b)
__global__ void lstm_ew(int t) {
    int idx = blockIdx.x * blockDim.x + threadIdx.x;
    int b = idx >> 10, j = idx & 1023;
    size_t gxr = (size_t)(t * BB + b) * G4 + j;
    size_t gr = (size_t)b * G4 + j;
    float gi = d_gates[gxr]        + d_gt[gr];
    float gf = d_gates[gxr + 1024] + d_gt[gr + 1024];
    float gg = d_gates[gxr + 2048] + d_gt[gr + 2048];
    float go = d_gates[gxr + 3072] + d_gt[gr + 3072];
    float i_ = 1.f / (1.f + expf(-gi));
    float f_ = 1.f / (1.f + expf(-gf));
    float g_ = tanhf(gg);
    float o_ = 1.f / (1.f + expf(-go));
    float c = i_ * g_ + (t ? f_ * d_c[idx] : 0.f);
    d_c[idx] = c;
    float h = o_ * tanhf(c);
    size_t hr = (size_t)(t * BB + b) * 1024 + j;
    h16 hh = __float2half(h);
    d_hfh[hr] = hh;
    d_hfl[hr] = __float2half(h - __half2float(hh));
}

// ---------------- HMMA GEMM (narrow, R8-proven) ----------------
// out[m][n] (+bias[n] when z==0) = sum_c Aseg[arow[m]]*Bseg[n] over chunk list.
// chunk c: seg = c / kps, kc = (c % kps) * 64. Row strides Astr/Bstr.
// BM=BN=128, 8 warps 2x4, 3-stage cp.async pipeline.
// blockIdx.z handles chunks [z*cpz,(z+1)*cpz).
// accum: epilogue uses atomicAdd instead of stores.
__global__ __launch_bounds__(256) void gemm_f16(
    const h16* __restrict__ A0, const h16* __restrict__ A1, const h16* __restrict__ A2,
    const h16* __restrict__ B0, const h16* __restrict__ B1, const h16* __restrict__ B2,
    const int* __restrict__ map, const float* __restrict__ bias,
    float* __restrict__ out, int M, int Ndim, int cpz,
    int m_base, int kps, int Astr, int Bstr, int accum)
{
    extern __shared__ char sm[];
    int* arow = reinterpret_cast<int*>(sm);
    uint32_t smu = smem_u32(sm);
    const uint32_t aA = smu + 1024;
    const uint32_t aB = aA + 3 * 16384;

    int tid = threadIdx.x;
    int lane = tid & 31;
    int w = tid >> 5;
    int wm = w >> 2, wn = w & 3;
    int n0 = blockIdx.x * 128;
    int m0 = m_base + blockIdx.y * 128;
    int c0 = blockIdx.z * cpz;
    int c1 = c0 + cpz;
    const float* bias_eff = (blockIdx.z == 0) ? bias : nullptr;

    if (tid < 128) {
        int mm = m0 + tid;
        if (mm >= M) mm = M - 1;
        arow[tid] = map ? map[mm] : mm;
    }
    __syncthreads();

    auto load_chunk = [&](int chunk, int stage) {
        int seg = chunk / kps;
        int kc = (chunk - seg * kps) * 64;
        const h16* Ap = (seg == 0) ? A0 : (seg == 1) ? A1 : A2;
        const h16* Bp = (seg == 0) ? B0 : (seg == 1) ? B1 : B2;
        uint32_t da = aA + stage * 16384;
        uint32_t db = aB + stage * 16384;
#pragma unroll
        for (int q = 0; q < 4; q++) {
            int idx = q * 256 + tid;
            int row = idx >> 3, c = idx & 7;
            const h16* src = Ap + (size_t)arow[row] * Astr + kc + c * 8;
            CP16(da + row * 128 + ((c ^ (row & 7)) * 16), src);
        }
#pragma unroll
        for (int q = 0; q < 4; q++) {
            int idx = q * 256 + tid;
            int row = idx >> 3, c = idx & 7;
            int vr = n0 + row;
            if (vr >= Ndim) vr = Ndim - 1;
            const h16* src = Bp + (size_t)vr * Bstr + kc + c * 8;
            CP16(db + row * 128 + ((c ^ (row & 7)) * 16), src);
        }
        CP_COMMIT();
    };

    float acc[4][4][4];
#pragma unroll
    for (int i = 0; i < 4; i++)
#pragma unroll
        for (int j = 0; j < 4; j++)
#pragma unroll
            for (int k = 0; k < 4; k++) acc[i][j][k] = 0.f;

    load_chunk(c0, 0);
    if (c0 + 1 < c1) load_chunk(c0 + 1, 1);

    int lrow = lane & 15;
    int lcol = lane >> 4;

    for (int i = c0; i < c1; i++) {
        if (i + 1 < c1) { CP_WAIT1(); } else { CP_WAIT0(); }
        __syncthreads();
        if (i + 2 < c1) load_chunk(i + 2, (i + 2 - c0) % 3);

        int stage = (i - c0) % 3;
        uint32_t ab = aA + stage * 16384;
        uint32_t bb = aB + stage * 16384;
#pragma unroll
        for (int k16 = 0; k16 < 4; k16++) {
            uint32_t af[4][4];
#pragma unroll
            for (int mt = 0; mt < 4; mt++) {
                int r = wm * 64 + mt * 16 + lrow;
                int c = (k16 * 2 + lcol) ^ (r & 7);
                ldsm4(ab + r * 128 + c * 16, af[mt]);
            }
            uint32_t bf[2][4];
#pragma unroll
            for (int bt = 0; bt < 2; bt++) {
                int r = wn * 32 + bt * 16 + lrow;
                int c = (k16 * 2 + lcol) ^ (r & 7);
                ldsm4(bb + r * 128 + c * 16, bf[bt]);
            }
#pragma unroll
            for (int mt = 0; mt < 4; mt++)
#pragma unroll
                for (int bt = 0; bt < 2; bt++) {
                    mma16816(acc[mt][bt * 2],     af[mt], bf[bt][0], bf[bt][2]);
                    mma16816(acc[mt][bt * 2 + 1], af[mt], bf[bt][1], bf[bt][3]);
                }
        }
        __syncthreads();
    }

    int gr = lane >> 2;
    int gc = (lane & 3) * 2;
#pragma unroll
    for (int mt = 0; mt < 4; mt++) {
        int r0 = m0 + wm * 64 + mt * 16 + gr;
        int r1 = r0 + 8;
#pragma unroll
        for (int j = 0; j < 4; j++) {
            int n = n0 + wn * 32 + j * 8 + gc;
            if (n >= Ndim) continue;
            if (accum) {
                if (r0 < M) {
                    atomicAdd(out + (size_t)r0 * Ndim + n,     acc[mt][j][0]);
                    atomicAdd(out + (size_t)r0 * Ndim + n + 1, acc[mt][j][1]);
                }
                if (r1 < M) {
                    atomicAdd(out + (size_t)r1 * Ndim + n,     acc[mt][j][2]);
                    atomicAdd(out + (size_t)r1 * Ndim + n + 1, acc[mt][j][3]);
                }
            } else {
                float bx = 0.f, by = 0.f;
                if (bias_eff) { float2 bv = *reinterpret_cast<const float2*>(bias_eff + n); bx = bv.x; by = bv.y; }
                if (r0 < M) {
                    float2 v = make_float2(acc[mt][j][0] + bx, acc[mt][j][1] + by);
                    *reinterpret_cast<float2*>(out + (size_t)r0 * Ndim + n) = v;
                }
                if (r1 < M) {
                    float2 v = make_float2(acc[mt][j][2] + bx, acc[mt][j][3] + by);
                    *reinterpret_cast<float2*>(out + (size_t)r1 * Ndim + n) = v;
                }
            }
        }
    }
}

// ---------------- launch ----------------
extern "C" void kernel_launch(void* const* d_in, const int* in_sizes, int n_in,
                              void* d_out, int out_size) {
    const float* features = (const float*)d_in[0];
    const float* tags     = (const float*)d_in[1];
    const int*   captions = (const int*)d_in[2];
    const int*   lengths  = (const int*)d_in[3];
    const float* W_embed  = (const float*)d_in[4];
    const float* W_ih     = (const float*)d_in[5];
    const float* W_hh     = (const float*)d_in[6];
    const float* b_ih     = (const float*)d_in[7];
    const float* b_hh     = (const float*)d_in[8];
    const float* W_lin    = (const float*)d_in[9];
    const float* b_lin    = (const float*)d_in[10];
    float* out = (float*)d_out;

    int N = out_size / VV;

    const int SMEM = 1024 + 3 * 16384 * 2;   // 99328
    static bool once = false;
    static cudaStream_t sA = 0, sB = 0;      // sA: hi-prio chain; sB: lo-prio bulk
    static cudaEvent_t evF, evW, evXp[5], evWL, evJA, evJB;
    if (!once) {
        cudaFuncSetAttribute(gemm_f16, cudaFuncAttributeMaxDynamicSharedMemorySize, SMEM);
        int lo, hi;
        cudaDeviceGetStreamPriorityRange(&lo, &hi);
        cudaStreamCreateWithPriority(&sA, cudaStreamNonBlocking, hi);
        cudaStreamCreateWithPriority(&sB, cudaStreamNonBlocking, lo);
        cudaEventCreateWithFlags(&evF, cudaEventDisableTiming);
        cudaEventCreateWithFlags(&evW, cudaEventDisableTiming);
        for (int g = 0; g < 5; g++) cudaEventCreateWithFlags(&evXp[g], cudaEventDisableTiming);
        cudaEventCreateWithFlags(&evWL, cudaEventDisableTiming);
        cudaEventCreateWithFlags(&evJA, cudaEventDisableTiming);
        cudaEventCreateWithFlags(&evJB, cudaEventDisableTiming);
        once = true;
    }

    h16 *p_hfh, *p_hfl, *p_xeh, *p_xel, *p_tgh, *p_tgl, *p_Wlf;
    h16 *p_Wieh, *p_Wiel, *p_With, *p_Witl, *p_Whhh, *p_Whhl;
    float *p_gates, *p_gt, *p_bias2;
    int* p_map;
    cudaGetSymbolAddress((void**)&p_hfh, d_hfh);
    cudaGetSymbolAddress((void**)&p_hfl, d_hfl);
    cudaGetSymbolAddress((void**)&p_xeh, d_xeh);
    cudaGetSymbolAddress((void**)&p_xel, d_xel);
    cudaGetSymbolAddress((void**)&p_tgh, d_tgh);
    cudaGetSymbolAddress((void**)&p_tgl, d_tgl);
    cudaGetSymbolAddress((void**)&p_Wlf, d_Wlf);
    cudaGetSymbolAddress((void**)&p_Wieh, d_Wieh);
    cudaGetSymbolAddress((void**)&p_Wiel, d_Wiel);
    cudaGetSymbolAddress((void**)&p_With, d_With);
    cudaGetSymbolAddress((void**)&p_Witl, d_Witl);
    cudaGetSymbolAddress((void**)&p_Whhh, d_Whhh);
    cudaGetSymbolAddress((void**)&p_Whhl, d_Whhl);
    cudaGetSymbolAddress((void**)&p_gates, d_gates);
    cudaGetSymbolAddress((void**)&p_gt, d_gt);
    cudaGetSymbolAddress((void**)&p_bias2, d_bias2);
    cudaGetSymbolAddress((void**)&p_map, d_rowmap);

    // fork worker streams
    cudaEventRecord(evF, 0);
    cudaStreamWaitEvent(sA, evF, 0);
    cudaStreamWaitEvent(sB, evF, 0);

    // ---- sB (lo-prio): W_ih split, x gather, gx in hybrid pieces
    //      (2 x 4-timestep for fast unlock, 3 x 8-timestep for efficiency),
    //      then W_lin conversion ----
    conv_wih<<<4096, 256, 0, sB>>>(W_ih);
    cudaEventRecord(evW, sB);
    conv_xt<<<4096, 128, 0, sB>>>(features, captions, W_embed);
    // piece 0: ts 0-3 (rows 0-511), 128 CTAs — lowest latency to unlock rec
    gemm_f16<<<dim3(32, 4, 1), 256, SMEM, sB>>>(
        p_xeh, p_xel, p_xeh, p_Wieh, p_Wieh, p_Wiel,
        nullptr, nullptr, p_gates, 4096, G4, 24, 0, 8, 512, 512, 0);
    cudaEventRecord(evXp[0], sB);
    // piece 1: ts 4-7 (rows 512-1023), 128 CTAs
    gemm_f16<<<dim3(32, 4, 1), 256, SMEM, sB>>>(
        p_xeh, p_xel, p_xeh, p_Wieh, p_Wieh, p_Wiel,
        nullptr, nullptr, p_gates, 4096, G4, 24, 512, 8, 512, 512, 0);
    cudaEventRecord(evXp[1], sB);
    // pieces 2-4: 8 timesteps each (256 CTAs, full 2/SM wave)
    for (int g = 0; g < 3; g++) {
        gemm_f16<<<dim3(32, 8, 1), 256, SMEM, sB>>>(
            p_xeh, p_xel, p_xeh, p_Wieh, p_Wieh, p_Wiel,
            nullptr, nullptr, p_gates, 4096, G4, 24, 1024 + 1024 * g, 8, 512, 512, 0);
        cudaEventRecord(evXp[2 + g], sB);
    }
    conv_round<<<(VV * 1024 / 4 + 255) / 256, 256, 0, sB>>>(W_lin, p_Wlf, VV * 1024 / 4);
    cudaEventRecord(evWL, sB);

    // ---- sA (hi-prio): meta, conversions, tag-gx, recurrence, projection ----
    meta_kernel<<<1, 128, 0, sA>>>(lengths);
    conv_split<<<4096, 256, 0, sA>>>(W_hh, p_Whhh, p_Whhl, 4096 * 1024 / 4);
    conv_tags<<<128, 128, 0, sA>>>(tags);
    bias2_k<<<16, 256, 0, sA>>>(b_ih, b_hh);
    cudaStreamWaitEvent(sA, evW, 0);
    // tag-gx: M=128 rows, single pass, includes bias2
    gemm_f16<<<dim3(32, 1, 1), 256, SMEM, sA>>>(
        p_tgh, p_tgl, p_tgh, p_With, p_With, p_Witl,
        nullptr, p_bias2, p_gt, BB, G4, 24, 0, 8, 512, 512, 0);

    for (int t = 0; t < TT; t++) {
        // gates: t=0 -> piece0 (ts 0-3), t=4 -> piece1 (ts 4-7),
        //        t=8/16/24 -> pieces 2/3/4 (8 ts each)
        if (t == 0) cudaStreamWaitEvent(sA, evXp[0], 0);
        else if (t == 4) cudaStreamWaitEvent(sA, evXp[1], 0);
        else if (t == 8) cudaStreamWaitEvent(sA, evXp[2], 0);
        else if (t == 16) cudaStreamWaitEvent(sA, evXp[3], 0);
        else if (t == 24) cudaStreamWaitEvent(sA, evXp[4], 0);
        if (t > 0) {
            const h16* ah = p_hfh + (size_t)(t - 1) * BB * 1024;
            const h16* al = p_hfl + (size_t)(t - 1) * BB * 1024;
            // 3 segs x 16 chunks = 48 chunks, z=8 -> 256 CTAs;
            // atomicAdd into d_gates rows of step t (on top of gx stores)
            gemm_f16<<<dim3(32, 1, 8), 256, SMEM, sA>>>(
                ah, al, ah, p_Whhh, p_Whhh, p_Whhl,
                nullptr, nullptr, p_gates + (size_t)t * BB * G4, BB, G4, 6,
                0, 16, 1024, 1024, 1);
        }
        lstm_ew<<<(BB * HH + 255) / 256, 256, 0, sA>>>(t);
    }

    // projection: single launch after recurrence (rows via rowmap, single fp16 pass)
    cudaStreamWaitEvent(sA, evWL, 0);
    gemm_f16<<<dim3((VV + 127) / 128, (N + 127) / 128, 1), 256, SMEM, sA>>>(
        p_hfh, p_hfh, p_hfh, p_Wlf, p_Wlf, p_Wlf,
        p_map, b_lin, out, N, VV, 16, 0, 16, 1024, 1024, 0);

    // join
    cudaEventRecord(evJA, sA);
    cudaEventRecord(evJB, sB);
    cudaStreamWaitEvent(0, evJA, 0);
    cudaStreamWaitEvent(0, evJB, 0);
}

// round 17
// speedup vs baseline: 1.0176x; 1.0176x over previous
#include <cuda_runtime.h>
#include <cuda_fp16.h>
#include <math.h>
#include <stdint.h>

#define BB 128
#define LL 31
#define TT 32
#define EE 512
#define TAGN 512
#define HH 1024
#define G4 4096
#define VV 30000

typedef __half h16;

// ---------------- device scratch ----------------
__device__ __align__(256) float d_gates[(size_t)4096 * 4096];   // gx (stores) + rec (atomics), rows t*128+b
__device__ __align__(256) float d_gt[(size_t)BB * G4];          // tag-gx + bias, rows b
__device__ __align__(256) float d_c[BB * HH];
__device__ __align__(256) h16 d_hfh[(size_t)4096 * 1024];       // h hi, rows t*128+b
__device__ __align__(256) h16 d_hfl[(size_t)4096 * 1024];       // h lo
__device__ __align__(256) h16 d_xeh[(size_t)4096 * 512];        // x embed-part hi, rows t*128+b
__device__ __align__(256) h16 d_xel[(size_t)4096 * 512];
__device__ __align__(256) h16 d_tgh[(size_t)BB * 512];          // tags hi/lo
__device__ __align__(256) h16 d_tgl[(size_t)BB * 512];
__device__ __align__(256) h16 d_Wlf[(size_t)VV * 1024];         // W_lin fp16
__device__ __align__(256) h16 d_Wieh[(size_t)4096 * 512];       // W_ih embed cols hi/lo
__device__ __align__(256) h16 d_Wiel[(size_t)4096 * 512];
__device__ __align__(256) h16 d_With[(size_t)4096 * 512];       // W_ih tag cols hi/lo
__device__ __align__(256) h16 d_Witl[(size_t)4096 * 512];
__device__ __align__(256) h16 d_Whhh[(size_t)4096 * 1024];      // W_hh hi/lo
__device__ __align__(256) h16 d_Whhl[(size_t)4096 * 1024];
__device__ __align__(256) float d_bias2[G4];
__device__ int d_rowmap[4096];

// ---------------- asm helpers (portable to plain sm_103) ----------------
__device__ __forceinline__ uint32_t smem_u32(const void* p) {
    uint32_t a;
    asm("{ .reg .u64 t; cvta.to.shared.u64 t, %1; cvt.u32.u64 %0, t; }" : "=r"(a) : "l"(p));
    return a;
}
#define CP16(dst, src) asm volatile("cp.async.cg.shared.global [%0], [%1], 16;" :: "r"(dst), "l"(src))
#define CP_COMMIT()    asm volatile("cp.async.commit_group;")
#define CP_WAIT1()     asm volatile("cp.async.wait_group 1;")
#define CP_WAIT0()     asm volatile("cp.async.wait_group 0;")

__device__ __forceinline__ void ldsm4(uint32_t addr, uint32_t* r) {
    asm volatile("ldmatrix.sync.aligned.m8n8.x4.shared.b16 {%0,%1,%2,%3}, [%4];"
                 : "=r"(r[0]), "=r"(r[1]), "=r"(r[2]), "=r"(r[3]) : "r"(addr));
}
__device__ __forceinline__ void mma16816(float* d, const uint32_t* a, uint32_t b0, uint32_t b1) {
    asm volatile(
        "mma.sync.aligned.m16n8k16.row.col.f32.f16.f16.f32 "
        "{%0,%1,%2,%3}, {%4,%5,%6,%7}, {%8,%9}, {%0,%1,%2,%3};"
        : "+f"(d[0]), "+f"(d[1]), "+f"(d[2]), "+f"(d[3])
        : "r"(a[0]), "r"(a[1]), "r"(a[2]), "r"(a[3]), "r"(b0), "r"(b1));
}

// ---------------- small kernels ----------------
__global__ void meta_kernel(const int* __restrict__ lengths) {
    __shared__ int len[BB];
    __shared__ int nt[TT];
    __shared__ int off[TT];
    int tid = threadIdx.x;
    len[tid] = lengths[tid];
    __syncthreads();
    if (tid < TT) {
        int c = 0;
        for (int b = 0; b < BB; b++) c += (len[b] > tid) ? 1 : 0;
        nt[tid] = c;
    }
    __syncthreads();
    if (tid == 0) {
        int s = 0;
        for (int t = 0; t < TT; t++) { off[t] = s; s += nt[t]; }
    }
    __syncthreads();
    for (int t = 0; t < TT; t++) {
        int n = nt[t], o = off[t];
        for (int b = tid; b < n; b += blockDim.x)
            d_rowmap[o + b] = t * BB + b;
    }
}

// generic fp32 -> fp16 hi/lo split
__global__ void conv_split(const float* __restrict__ s, h16* __restrict__ hi,
                           h16* __restrict__ lo, int n4) {
    int i = blockIdx.x * blockDim.x + threadIdx.x;
    if (i >= n4) return;
    float4 v = reinterpret_cast<const float4*>(s)[i];
    float vv[4] = {v.x, v.y, v.z, v.w};
    h16 hh[4], ll[4];
#pragma unroll
    for (int j = 0; j < 4; j++) {
        hh[j] = __float2half(vv[j]);
        ll[j] = __float2half(vv[j] - __half2float(hh[j]));
    }
    reinterpret_cast<uint2*>(hi)[i] = *reinterpret_cast<uint2*>(hh);
    reinterpret_cast<uint2*>(lo)[i] = *reinterpret_cast<uint2*>(ll);
}

// fp32 -> fp16 round (single)
__global__ void conv_round(const float* __restrict__ s, h16* __restrict__ o, int n4) {
    int i = blockIdx.x * blockDim.x + threadIdx.x;
    if (i >= n4) return;
    float4 v = reinterpret_cast<const float4*>(s)[i];
    h16 hh[4] = {__float2half(v.x), __float2half(v.y), __float2half(v.z), __float2half(v.w)};
    reinterpret_cast<uint2*>(o)[i] = *reinterpret_cast<uint2*>(hh);
}

// split W_ih [4096][1024] column-wise into embed (k<512) and tag (k>=512) hi/lo
__global__ void conv_wih(const float* __restrict__ W_ih) {
    int row = blockIdx.x;
    int k = threadIdx.x * 4;
    float4 v = *reinterpret_cast<const float4*>(W_ih + (size_t)row * 1024 + k);
    float vv[4] = {v.x, v.y, v.z, v.w};
    h16 hh[4], ll[4];
#pragma unroll
    for (int j = 0; j < 4; j++) {
        hh[j] = __float2half(vv[j]);
        ll[j] = __float2half(vv[j] - __half2float(hh[j]));
    }
    if (k < EE) {
        size_t o = ((size_t)row * 512 + k) >> 2;
        reinterpret_cast<uint2*>(d_Wieh)[o] = *reinterpret_cast<uint2*>(hh);
        reinterpret_cast<uint2*>(d_Wiel)[o] = *reinterpret_cast<uint2*>(ll);
    } else {
        size_t o = ((size_t)row * 512 + (k - EE)) >> 2;
        reinterpret_cast<uint2*>(d_With)[o] = *reinterpret_cast<uint2*>(hh);
        reinterpret_cast<uint2*>(d_Witl)[o] = *reinterpret_cast<uint2*>(ll);
    }
}

__global__ void bias2_k(const float* __restrict__ b_ih, const float* __restrict__ b_hh) {
    int i = blockIdx.x * blockDim.x + threadIdx.x;
    if (i < G4) d_bias2[i] = b_ih[i] + b_hh[i];
}

// gather embed-part x rows (features for t=0, embeddings else), rows t*128+b
__global__ void conv_xt(const float* __restrict__ features,
                        const int* __restrict__ captions, const float* __restrict__ W_embed) {
    int r = blockIdx.x;
    int t = r >> 7, b = r & 127;
    int k = threadIdx.x * 4;
    const float* src = (t == 0) ? (features + (size_t)b * EE)
                                : (W_embed + (size_t)captions[b * LL + (t - 1)] * EE);
    float4 v = *reinterpret_cast<const float4*>(src + k);
    float vv[4] = {v.x, v.y, v.z, v.w};
    h16 hh[4], ll[4];
#pragma unroll
    for (int j = 0; j < 4; j++) {
        hh[j] = __float2half(vv[j]);
        ll[j] = __float2half(vv[j] - __half2float(hh[j]));
    }
    size_t o = ((size_t)r * 512 + k) >> 2;
    reinterpret_cast<uint2*>(d_xeh)[o] = *reinterpret_cast<uint2*>(hh);
    reinterpret_cast<uint2*>(d_xel)[o] = *reinterpret_cast<uint2*>(ll);
}

// split tags [128][512] hi/lo
__global__ void conv_tags(const float* __restrict__ tags) {
    int b = blockIdx.x;
    int k = threadIdx.x * 4;
    float4 v = *reinterpret_cast<const float4*>(tags + (size_t)b * TAGN + k);
    float vv[4] = {v.x, v.y, v.z, v.w};
    h16 hh[4], ll[4];
#pragma unroll
    for (int j = 0; j < 4; j++) {
        hh[j] = __float2half(vv[j]);
        ll[j] = __float2half(vv[j] - __half2float(hh[j]));
    }
    size_t o = ((size_t)b * 512 + k) >> 2;
    reinterpret_cast<uint2*>(d_tgh)[o] = *reinterpret_cast<uint2*>(hh);
    reinterpret_cast<uint2*>(d_tgl)[o] = *reinterpret_cast<uint2*>(ll);
}

// LSTM elementwise: gates = d_gates(row t*128+b; gx stores + rec atomics) + d_gt(row b)
__global__ void lstm_ew(int t) {
    int idx = blockIdx.x * blockDim.x + threadIdx.x;
    int b = idx >> 10, j = idx & 1023;
    size_t gxr = (size_t)(t * BB + b) * G4 + j;
    size_t gr = (size_t)b * G4 + j;
    float gi = d_gates[gxr]        + d_gt[gr];
    float gf = d_gates[gxr + 1024] + d_gt[gr + 1024];
    float gg = d_gates[gxr + 2048] + d_gt[gr + 2048];
    float go = d_gates[gxr + 3072] + d_gt[gr + 3072];
    float i_ = 1.f / (1.f + expf(-gi));
    float f_ = 1.f / (1.f + expf(-gf));
    float g_ = tanhf(gg);
    float o_ = 1.f / (1.f + expf(-go));
    float c = i_ * g_ + (t ? f_ * d_c[idx] : 0.f);
    d_c[idx] = c;
    float h = o_ * tanhf(c);
    size_t hr = (size_t)(t * BB + b) * 1024 + j;
    h16 hh = __float2half(h);
    d_hfh[hr] = hh;
    d_hfl[hr] = __float2half(h - __half2float(hh));
}

// ---------------- HMMA GEMM (narrow, R8-proven) ----------------
// out[m][n] (+bias[n] when z==0) = sum_c Aseg[arow[m]]*Bseg[n] over chunk list.
// chunk c: seg = c / kps, kc = (c % kps) * 64. Row strides Astr/Bstr.
// BM=BN=128, 8 warps 2x4, 3-stage cp.async pipeline.
// blockIdx.z handles chunks [z*cpz,(z+1)*cpz).
// accum: epilogue uses atomicAdd instead of stores.
__global__ __launch_bounds__(256) void gemm_f16(
    const h16* __restrict__ A0, const h16* __restrict__ A1, const h16* __restrict__ A2,
    const h16* __restrict__ B0, const h16* __restrict__ B1, const h16* __restrict__ B2,
    const int* __restrict__ map, const float* __restrict__ bias,
    float* __restrict__ out, int M, int Ndim, int cpz,
    int m_base, int kps, int Astr, int Bstr, int accum)
{
    extern __shared__ char sm[];
    int* arow = reinterpret_cast<int*>(sm);
    uint32_t smu = smem_u32(sm);
    const uint32_t aA = smu + 1024;
    const uint32_t aB = aA + 3 * 16384;

    int tid = threadIdx.x;
    int lane = tid & 31;
    int w = tid >> 5;
    int wm = w >> 2, wn = w & 3;
    int n0 = blockIdx.x * 128;
    int m0 = m_base + blockIdx.y * 128;
    int c0 = blockIdx.z * cpz;
    int c1 = c0 + cpz;
    const float* bias_eff = (blockIdx.z == 0) ? bias : nullptr;

    if (tid < 128) {
        int mm = m0 + tid;
        if (mm >= M) mm = M - 1;
        arow[tid] = map ? map[mm] : mm;
    }
    __syncthreads();

    auto load_chunk = [&](int chunk, int stage) {
        int seg = chunk / kps;
        int kc = (chunk - seg * kps) * 64;
        const h16* Ap = (seg == 0) ? A0 : (seg == 1) ? A1 : A2;
        const h16* Bp = (seg == 0) ? B0 : (seg == 1) ? B1 : B2;
        uint32_t da = aA + stage * 16384;
        uint32_t db = aB + stage * 16384;
#pragma unroll
        for (int q = 0; q < 4; q++) {
            int idx = q * 256 + tid;
            int row = idx >> 3, c = idx & 7;
            const h16* src = Ap + (size_t)arow[row] * Astr + kc + c * 8;
            CP16(da + row * 128 + ((c ^ (row & 7)) * 16), src);
        }
#pragma unroll
        for (int q = 0; q < 4; q++) {
            int idx = q * 256 + tid;
            int row = idx >> 3, c = idx & 7;
            int vr = n0 + row;
            if (vr >= Ndim) vr = Ndim - 1;
            const h16* src = Bp + (size_t)vr * Bstr + kc + c * 8;
            CP16(db + row * 128 + ((c ^ (row & 7)) * 16), src);
        }
        CP_COMMIT();
    };

    float acc[4][4][4];
#pragma unroll
    for (int i = 0; i < 4; i++)
#pragma unroll
        for (int j = 0; j < 4; j++)
#pragma unroll
            for (int k = 0; k < 4; k++) acc[i][j][k] = 0.f;

    load_chunk(c0, 0);
    if (c0 + 1 < c1) load_chunk(c0 + 1, 1);

    int lrow = lane & 15;
    int lcol = lane >> 4;

    for (int i = c0; i < c1; i++) {
        if (i + 1 < c1) { CP_WAIT1(); } else { CP_WAIT0(); }
        __syncthreads();
        if (i + 2 < c1) load_chunk(i + 2, (i + 2 - c0) % 3);

        int stage = (i - c0) % 3;
        uint32_t ab = aA + stage * 16384;
        uint32_t bb = aB + stage * 16384;
#pragma unroll
        for (int k16 = 0; k16 < 4; k16++) {
            uint32_t af[4][4];
#pragma unroll
            for (int mt = 0; mt < 4; mt++) {
                int r = wm * 64 + mt * 16 + lrow;
                int c = (k16 * 2 + lcol) ^ (r & 7);
                ldsm4(ab + r * 128 + c * 16, af[mt]);
            }
            uint32_t bf[2][4];
#pragma unroll
            for (int bt = 0; bt < 2; bt++) {
                int r = wn * 32 + bt * 16 + lrow;
                int c = (k16 * 2 + lcol) ^ (r & 7);
                ldsm4(bb + r * 128 + c * 16, bf[bt]);
            }
#pragma unroll
            for (int mt = 0; mt < 4; mt++)
#pragma unroll
                for (int bt = 0; bt < 2; bt++) {
                    mma16816(acc[mt][bt * 2],     af[mt], bf[bt][0], bf[bt][2]);
                    mma16816(acc[mt][bt * 2 + 1], af[mt], bf[bt][1], bf[bt][3]);
                }
        }
        __syncthreads();
    }

    int gr = lane >> 2;
    int gc = (lane & 3) * 2;
#pragma unroll
    for (int mt = 0; mt < 4; mt++) {
        int r0 = m0 + wm * 64 + mt * 16 + gr;
        int r1 = r0 + 8;
#pragma unroll
        for (int j = 0; j < 4; j++) {
            int n = n0 + wn * 32 + j * 8 + gc;
            if (n >= Ndim) continue;
            if (accum) {
                if (r0 < M) {
                    atomicAdd(out + (size_t)r0 * Ndim + n,     acc[mt][j][0]);
                    atomicAdd(out + (size_t)r0 * Ndim + n + 1, acc[mt][j][1]);
                }
                if (r1 < M) {
                    atomicAdd(out + (size_t)r1 * Ndim + n,     acc[mt][j][2]);
                    atomicAdd(out + (size_t)r1 * Ndim + n + 1, acc[mt][j][3]);
                }
            } else {
                float bx = 0.f, by = 0.f;
                if (bias_eff) { float2 bv = *reinterpret_cast<const float2*>(bias_eff + n); bx = bv.x; by = bv.y; }
                if (r0 < M) {
                    float2 v = make_float2(acc[mt][j][0] + bx, acc[mt][j][1] + by);
                    *reinterpret_cast<float2*>(out + (size_t)r0 * Ndim + n) = v;
                }
                if (r1 < M) {
                    float2 v = make_float2(acc[mt][j][2] + bx, acc[mt][j][3] + by);
                    *reinterpret_cast<float2*>(out + (size_t)r1 * Ndim + n) = v;
                }
            }
        }
    }
}

// ---------------- launch ----------------
extern "C" void kernel_launch(void* const* d_in, const int* in_sizes, int n_in,
                              void* d_out, int out_size) {
    const float* features = (const float*)d_in[0];
    const float* tags     = (const float*)d_in[1];
    const int*   captions = (const int*)d_in[2];
    const int*   lengths  = (const int*)d_in[3];
    const float* W_embed  = (const float*)d_in[4];
    const float* W_ih     = (const float*)d_in[5];
    const float* W_hh     = (const float*)d_in[6];
    const float* b_ih     = (const float*)d_in[7];
    const float* b_hh     = (const float*)d_in[8];
    const float* W_lin    = (const float*)d_in[9];
    const float* b_lin    = (const float*)d_in[10];
    float* out = (float*)d_out;

    int N = out_size / VV;

    const int SMEM = 1024 + 3 * 16384 * 2;   // 99328
    static bool once = false;
    static cudaStream_t sA = 0, sB = 0;      // sA: hi-prio chain; sB: lo-prio bulk
    static cudaEvent_t evF, evW, evXp[4], evWL, evJA, evJB;
    if (!once) {
        cudaFuncSetAttribute(gemm_f16, cudaFuncAttributeMaxDynamicSharedMemorySize, SMEM);
        int lo, hi;
        cudaDeviceGetStreamPriorityRange(&lo, &hi);
        cudaStreamCreateWithPriority(&sA, cudaStreamNonBlocking, hi);
        cudaStreamCreateWithPriority(&sB, cudaStreamNonBlocking, lo);
        cudaEventCreateWithFlags(&evF, cudaEventDisableTiming);
        cudaEventCreateWithFlags(&evW, cudaEventDisableTiming);
        for (int g = 0; g < 4; g++) cudaEventCreateWithFlags(&evXp[g], cudaEventDisableTiming);
        cudaEventCreateWithFlags(&evWL, cudaEventDisableTiming);
        cudaEventCreateWithFlags(&evJA, cudaEventDisableTiming);
        cudaEventCreateWithFlags(&evJB, cudaEventDisableTiming);
        once = true;
    }

    h16 *p_hfh, *p_hfl, *p_xeh, *p_xel, *p_tgh, *p_tgl, *p_Wlf;
    h16 *p_Wieh, *p_Wiel, *p_With, *p_Witl, *p_Whhh, *p_Whhl;
    float *p_gates, *p_gt, *p_bias2;
    int* p_map;
    cudaGetSymbolAddress((void**)&p_hfh, d_hfh);
    cudaGetSymbolAddress((void**)&p_hfl, d_hfl);
    cudaGetSymbolAddress((void**)&p_xeh, d_xeh);
    cudaGetSymbolAddress((void**)&p_xel, d_xel);
    cudaGetSymbolAddress((void**)&p_tgh, d_tgh);
    cudaGetSymbolAddress((void**)&p_tgl, d_tgl);
    cudaGetSymbolAddress((void**)&p_Wlf, d_Wlf);
    cudaGetSymbolAddress((void**)&p_Wieh, d_Wieh);
    cudaGetSymbolAddress((void**)&p_Wiel, d_Wiel);
    cudaGetSymbolAddress((void**)&p_With, d_With);
    cudaGetSymbolAddress((void**)&p_Witl, d_Witl);
    cudaGetSymbolAddress((void**)&p_Whhh, d_Whhh);
    cudaGetSymbolAddress((void**)&p_Whhl, d_Whhl);
    cudaGetSymbolAddress((void**)&p_gates, d_gates);
    cudaGetSymbolAddress((void**)&p_gt, d_gt);
    cudaGetSymbolAddress((void**)&p_bias2, d_bias2);
    cudaGetSymbolAddress((void**)&p_map, d_rowmap);

    // fork worker streams
    cudaEventRecord(evF, 0);
    cudaStreamWaitEvent(sA, evF, 0);
    cudaStreamWaitEvent(sB, evF, 0);

    // ---- sB (lo-prio): W_ih split, x gather, gx in 4 pieces of 8 timesteps,
    //      then W_lin conversion ----
    conv_wih<<<4096, 256, 0, sB>>>(W_ih);
    cudaEventRecord(evW, sB);
    conv_xt<<<4096, 128, 0, sB>>>(features, captions, W_embed);
    for (int g = 0; g < 4; g++) {
        // piece g: rows [1024g, 1024g+1024) = timesteps 8g..8g+7, single-pass 24 chunks
        gemm_f16<<<dim3(32, 8, 1), 256, SMEM, sB>>>(
            p_xeh, p_xel, p_xeh, p_Wieh, p_Wieh, p_Wiel,
            nullptr, nullptr, p_gates, 4096, G4, 24, 1024 * g, 8, 512, 512, 0);
        cudaEventRecord(evXp[g], sB);
    }
    conv_round<<<(VV * 1024 / 4 + 255) / 256, 256, 0, sB>>>(W_lin, p_Wlf, VV * 1024 / 4);
    cudaEventRecord(evWL, sB);

    // ---- sA (hi-prio): meta, conversions, tag-gx, recurrence, projection ----
    meta_kernel<<<1, 128, 0, sA>>>(lengths);
    conv_split<<<4096, 256, 0, sA>>>(W_hh, p_Whhh, p_Whhl, 4096 * 1024 / 4);
    conv_tags<<<128, 128, 0, sA>>>(tags);
    bias2_k<<<16, 256, 0, sA>>>(b_ih, b_hh);
    cudaStreamWaitEvent(sA, evW, 0);
    // tag-gx: M=128 rows, single pass, includes bias2
    gemm_f16<<<dim3(32, 1, 1), 256, SMEM, sA>>>(
        p_tgh, p_tgl, p_tgh, p_With, p_With, p_Witl,
        nullptr, p_bias2, p_gt, BB, G4, 24, 0, 8, 512, 512, 0);

    for (int t = 0; t < TT; t++) {
        if ((t & 7) == 0) cudaStreamWaitEvent(sA, evXp[t >> 3], 0);
        if (t > 0) {
            const h16* ah = p_hfh + (size_t)(t - 1) * BB * 1024;
            const h16* al = p_hfl + (size_t)(t - 1) * BB * 1024;
            // 3 segs x 16 chunks = 48 chunks, z=8 -> 256 CTAs;
            // atomicAdd into d_gates rows of step t (on top of gx stores)
            gemm_f16<<<dim3(32, 1, 8), 256, SMEM, sA>>>(
                ah, al, ah, p_Whhh, p_Whhh, p_Whhl,
                nullptr, nullptr, p_gates + (size_t)t * BB * G4, BB, G4, 6,
                0, 16, 1024, 1024, 1);
        }
        lstm_ew<<<(BB * HH + 255) / 256, 256, 0, sA>>>(t);
    }

    // projection: single launch after recurrence (rows via rowmap, single fp16 pass)
    cudaStreamWaitEvent(sA, evWL, 0);
    gemm_f16<<<dim3((VV + 127) / 128, (N + 127) / 128, 1), 256, SMEM, sA>>>(
        p_hfh, p_hfh, p_hfh, p_Wlf, p_Wlf, p_Wlf,
        p_map, b_lin, out, N, VV, 16, 0, 16, 1024, 1024, 0);

    // join
    cudaEventRecord(evJA, sA);
    cudaEventRecord(evJB, sB);
    cudaStreamWaitEvent(0, evJA, 0);
    cudaStreamWaitEvent(0, evJB, 0);
}